// round 15
// baseline (speedup 1.0000x reference)
#include <cuda_runtime.h>
#include <cstdint>

#define KSEL   100
#define ESTR   128
#define BMAX   256
#define CAP    2048
#define TPBF   256
#define TPBS   256
#define SEGCAP 128
#define CHUNK  16384           // bytes per TMA stage
#define SEGB   (2 * CHUNK)     // bytes per filter CTA
#define T0     9.0f            // filter threshold; exact fallback covers any input

// Scratch (__device__ globals; zero-init at load; g_cnt reset by select each
// invocation -> graph replays deterministic; ranks are order-independent).
__device__ int                g_cnt[BMAX];
__device__ unsigned long long g_buf[BMAX * CAP];
__device__ float              g_exps[BMAX * ESTR];
__device__ int                g_inds[BMAX * KSEL];

// Order-preserving float->uint key: bigger float => bigger key.
__device__ __forceinline__ unsigned fkey(float f) {
    unsigned u = __float_as_uint(f);
    return u ^ (unsigned)(((int)u >> 31) | 0x80000000);
}
__device__ __forceinline__ float fkey_inv(unsigned kk) {
    unsigned u = (kk & 0x80000000u) ? (kk ^ 0x80000000u) : ~kk;
    return __uint_as_float(u);
}
__device__ __forceinline__ unsigned smem_u32(const void* p) {
    return (unsigned)__cvta_generic_to_shared(p);
}
__device__ __forceinline__ void mbar_init(unsigned mbar, unsigned cnt) {
    asm volatile("mbarrier.init.shared.b64 [%0], %1;" :: "r"(mbar), "r"(cnt) : "memory");
}
__device__ __forceinline__ void mbar_expect_tx(unsigned mbar, unsigned bytes) {
    asm volatile("mbarrier.arrive.expect_tx.shared.b64 _, [%0], %1;"
                 :: "r"(mbar), "r"(bytes) : "memory");
}
__device__ __forceinline__ void bulk_ld(unsigned dst, const void* src,
                                        unsigned bytes, unsigned mbar) {
    asm volatile(
        "cp.async.bulk.shared::cluster.global.mbarrier::complete_tx::bytes "
        "[%0], [%1], %2, [%3];"
        :: "r"(dst), "l"(src), "r"(bytes), "r"(mbar) : "memory");
}
__device__ __forceinline__ void mbar_wait(unsigned mbar, unsigned parity) {
    unsigned done;
    asm volatile(
        "{\n\t.reg .pred p;\n\t"
        "mbarrier.try_wait.parity.acquire.cta.shared::cta.b64 p, [%1], %2;\n\t"
        "selp.b32 %0, 1, 0, p;\n\t}"
        : "=r"(done) : "r"(mbar), "r"(parity) : "memory");
    if (!done) {
        asm volatile(
            "{\n\t.reg .pred P1;\n\t"
            "WL_%=:\n\t"
            "mbarrier.try_wait.parity.acquire.cta.shared::cta.b64 P1, [%0], %1, 0x989680;\n\t"
            "@P1 bra.uni WD_%=;\n\t"
            "bra.uni WL_%=;\n\t"
            "WD_%=:\n\t}"
            :: "r"(mbar), "r"(parity) : "memory");
    }
}

// ---------------------------------------------------------------------------
// Kernel 1: TMA double-buffered threshold filter (byte-identical to round 12).
// ---------------------------------------------------------------------------
__global__ __launch_bounds__(TPBF)
void filter_kernel(const float* __restrict__ logits, int V) {
    extern __shared__ __align__(128) char dyn[];          // 2*CHUNK bytes
    const int b   = blockIdx.x;
    const int s   = blockIdx.y;
    const int tid = threadIdx.x;
    const float* row = logits + (size_t)b * V;
    const int    V4  = V >> 2;
    const int    rowBytes = V4 << 4;

    __shared__ unsigned long long s_mbar[2];
    __shared__ unsigned s_n;
    __shared__ int s_base;
    __shared__ unsigned long long s_loc[SEGCAP];

    const int segBase = s * SEGB;
    const int size0 = min(CHUNK, rowBytes - segBase);
    const int size1 = min(CHUNK, rowBytes - segBase - size0);

    if (tid == 0) {
        s_n = 0;
        mbar_init(smem_u32(&s_mbar[0]), 1);
        mbar_init(smem_u32(&s_mbar[1]), 1);
    }
    __syncthreads();

    if (tid == 0) {
        mbar_expect_tx(smem_u32(&s_mbar[0]), (unsigned)size0);
        bulk_ld(smem_u32(dyn), (const char*)row + segBase,
                (unsigned)size0, smem_u32(&s_mbar[0]));
        if (size1 > 0) {
            mbar_expect_tx(smem_u32(&s_mbar[1]), (unsigned)size1);
            bulk_ld(smem_u32(dyn) + CHUNK, (const char*)row + segBase + size0,
                    (unsigned)size1, smem_u32(&s_mbar[1]));
        }
    }

#pragma unroll
    for (int c = 0; c < 2; c++) {
        const int szc = (c == 0) ? size0 : size1;
        if (szc <= 0) break;
        mbar_wait(smem_u32(&s_mbar[c]), 0);
        const float4* bufc = (const float4*)(dyn + c * CHUNK);
        const int nq = szc >> 4;
        const int qstart = (segBase >> 4) + c * (CHUNK >> 4);
        for (int i = tid; i < nq; i += TPBF) {
            float4 v = bufc[i];
            float m = fmaxf(fmaxf(v.x, v.y), fmaxf(v.z, v.w));
            if (m > T0) {                         // rare (~0.5% of quads)
                const int base = (qstart + i) * 4;
                float vv[4] = {v.x, v.y, v.z, v.w};
#pragma unroll
                for (int q = 0; q < 4; q++) {
                    if (vv[q] > T0) {
                        unsigned p = atomicAdd(&s_n, 1u);
                        if (p < SEGCAP)
                            s_loc[p] = ((unsigned long long)fkey(vv[q]) << 32) |
                                       (unsigned)(0xFFFFFFFFu - (unsigned)(base + q));
                    }
                }
            }
        }
    }
    if (s == 0) {                                 // scalar tail (V % 4)
        for (int i = V4 * 4 + tid; i < V; i += TPBF) {
            float x = row[i];
            if (x > T0) {
                unsigned p = atomicAdd(&s_n, 1u);
                if (p < SEGCAP)
                    s_loc[p] = ((unsigned long long)fkey(x) << 32) |
                               (unsigned)(0xFFFFFFFFu - (unsigned)i);
            }
        }
    }
    __syncthreads();

    if (tid == 0) {
        unsigned nsu = s_n;
        int add = (nsu > SEGCAP) ? 1000000 : (int)nsu;   // poison -> fallback
        s_base = atomicAdd(&g_cnt[b], add);
    }
    __syncthreads();
    int ns = min((int)s_n, SEGCAP);
    unsigned long long* buf = g_buf + (size_t)b * CAP;
    for (int t = tid; t < ns; t += TPBF) {
        int pos = s_base + t;
        if (pos < CAP) buf[pos] = s_loc[t];
    }
}

// ---------------------------------------------------------------------------
// Kernel 2: rank-by-counting selection (round-11 proven form, standalone).
// ---------------------------------------------------------------------------
__global__ __launch_bounds__(TPBS)
void select_kernel(const float* __restrict__ sp, int V,
                   const float* __restrict__ logits) {
    const int b    = blockIdx.x;
    const int tid  = threadIdx.x;
    const int lane = tid & 31;
    const int wid  = tid >> 5;

    __shared__ unsigned long long s_cand[512];
    __shared__ unsigned long long s_top;
    __shared__ unsigned s_nc;
    __shared__ int s_part[TPBS / 32];

    const int n = g_cnt[b];
    __syncthreads();                    // all threads read n before reset
    if (tid == 0) g_cnt[b] = 0;         // reset for next replay

    const float* row = logits + (size_t)b * V;
    int nc;

    if (n >= KSEL && n <= 512) {
        const unsigned long long* buf = g_buf + (size_t)b * CAP;
        s_cand[tid]       = (tid < n)       ? buf[tid]       : 0ull;
        s_cand[tid + 256] = (tid + 256 < n) ? buf[tid + 256] : 0ull;
        nc = n;
        __syncthreads();
    } else {
        // exact fallback: bitwise binary search for the 100th key over the row
        unsigned X = 0;
        for (int bit = 31; bit >= 0; --bit) {
            unsigned trial = X | (1u << bit);
            int local = 0;
            for (int i = tid; i < V; i += TPBS)
                local += (fkey(row[i]) >= trial);
#pragma unroll
            for (int off = 16; off; off >>= 1)
                local += __shfl_down_sync(0xffffffffu, local, off);
            if (lane == 0) s_part[wid] = local;
            __syncthreads();
            int cnt = 0;
#pragma unroll
            for (int w = 0; w < TPBS / 32; w++) cnt += s_part[w];
            __syncthreads();
            if (cnt >= KSEL) X = trial;
        }
        if (tid == 0) s_nc = 0;
        s_cand[tid] = 0ull;
        s_cand[tid + 256] = 0ull;
        __syncthreads();
        for (int i = tid; i < V; i += TPBS) {
            unsigned kk = fkey(row[i]);
            if (kk >= X) {
                unsigned p = atomicAdd(&s_nc, 1u);
                if (p < 512)
                    s_cand[p] = ((unsigned long long)kk << 32) |
                                (unsigned)(0xFFFFFFFFu - (unsigned)i);
            }
        }
        __syncthreads();
        nc = min((int)s_nc, 512);
    }

    // ranks via broadcast loop (all lanes read same address -> conflict-free)
    unsigned long long my0 = s_cand[tid];
    unsigned long long my1 = s_cand[tid + 256];
    int r0 = 0, r1 = 0;
    for (int j = 0; j < nc; j++) {
        unsigned long long cj = s_cand[j];
        r0 += (cj > my0);
        r1 += (cj > my1);
    }
    if (tid < nc       && r0 == 0) s_top = my0;
    if (tid + 256 < nc && r1 == 0) s_top = my1;
    if (tid < ESTR) g_exps[b * ESTR + tid] = 0.f;     // zero-pad exps
    __syncthreads();

    const float v0 = fkey_inv((unsigned)(s_top >> 32));
    const int   k  = min(max((int)sp[b * 3 + 0], 1), KSEL);
    const float T  = sp[b * 3 + 2];
    const float v0T = v0 / T;

    if (tid < nc && r0 < KSEL) {
        float val = fkey_inv((unsigned)(my0 >> 32));
        g_inds[b * KSEL + r0] = (int)(0xFFFFFFFFu - (unsigned)(my0 & 0xFFFFFFFFu));
        g_exps[b * ESTR + r0] = (r0 < k) ? expf(val / T - v0T) : 0.f;
    }
    if (tid + 256 < nc && r1 < KSEL) {
        float val = fkey_inv((unsigned)(my1 >> 32));
        g_inds[b * KSEL + r1] = (int)(0xFFFFFFFFu - (unsigned)(my1 & 0xFFFFFFFFu));
        g_exps[b * ESTR + r1] = (r1 < k) ? expf(val / T - v0T) : 0.f;
    }
}

// ---------------------------------------------------------------------------
// Kernel 3: warp-per-row sampling (round-11 proven form).
// ---------------------------------------------------------------------------
__global__ __launch_bounds__(1024)
void sample_kernel(const float* __restrict__ sp, int B,
                   float* __restrict__ out) {
    const int tid  = threadIdx.x;
    const int w    = tid >> 5;
    const int lane = tid & 31;
    const int NW   = blockDim.x >> 5;
    __shared__ float s_inv[1024];

    for (int r = w; r < B; r += NW) {
        const float* e = g_exps + r * ESTR;
        float s = 0.f;
#pragma unroll
        for (int c = 0; c < 4; c++) s += e[c * 32 + lane];
#pragma unroll
        for (int off = 16; off; off >>= 1)
            s += __shfl_xor_sync(0xffffffffu, s, off);
        if (lane == 0) s_inv[r] = 1.0f / s;   // csum[r][0]
    }
    __syncthreads();

    // jnp.min(csum) over the whole matrix = min_b 1/S_b
    float m = s_inv[0];
    for (int i = 1; i < B; i++) m = fminf(m, s_inv[i]);

    for (int r = w; r < B; r += NW) {
        const float* e = g_exps + r * ESTR;
        int   k    = min(max((int)sp[r * 3 + 0], 1), KSEL);
        float topp = sp[r * 3 + 1];
        float eff  = fmaxf(m, topp);

        float p[4];
        float carry = 0.f;
#pragma unroll
        for (int c = 0; c < 4; c++) {
            float x = e[c * 32 + lane];
#pragma unroll
            for (int off = 1; off < 32; off <<= 1) {
                float y = __shfl_up_sync(0xffffffffu, x, off);
                if (lane >= off) x += y;
            }
            float pv = x + carry;
            p[c] = pv;
            carry = __shfl_sync(0xffffffffu, pv, 31);
        }
        float S = carry;
        float invS = 1.0f / S;

        int ns = 0;
#pragma unroll
        for (int c = 0; c < 4; c++) {
            int gi = c * 32 + lane;
            bool cond = (gi < k) && (p[c] * invS <= eff);
            ns += __popc(__ballot_sync(0xffffffffu, cond));
        }
        if (ns < 1) ns = 1;

        int j = ns - 1, cc = j >> 5, ll = j & 31;
        float t0 = __shfl_sync(0xffffffffu, p[0], ll);
        float t1 = __shfl_sync(0xffffffffu, p[1], ll);
        float t2 = __shfl_sync(0xffffffffu, p[2], ll);
        float t3 = __shfl_sync(0xffffffffu, p[3], ll);
        float S2 = (cc == 0) ? t0 : (cc == 1) ? t1 : (cc == 2) ? t2 : t3;

        float half = 0.5f * S2;
        int cnt = 0;
#pragma unroll
        for (int c = 0; c < 4; c++) {
            int gi = c * 32 + lane;
            bool cond = (gi < ns) && (p[c] < half);
            cnt += __popc(__ballot_sync(0xffffffffu, cond));
        }
        if (cnt > ns - 1) cnt = ns - 1;
        if (cnt < 0) cnt = 0;

        if (lane == 0) out[r] = (float)g_inds[r * KSEL + cnt];
    }
}

// ---------------------------------------------------------------------------
extern "C" void kernel_launch(void* const* d_in, const int* in_sizes, int n_in,
                              void* d_out, int out_size) {
    int li = 0, si = 1;
    if (n_in >= 2 && in_sizes[0] < in_sizes[1]) { li = 1; si = 0; }
    const float* logits = (const float*)d_in[li];
    const float* sp     = (const float*)d_in[si];
    int B = in_sizes[si] / 3;
    int V = in_sizes[li] / B;
    if (B > BMAX) B = BMAX;

    int rowBytes = (V >> 2) << 4;
    int nseg = (rowBytes + SEGB - 1) / SEGB;     // 16 for V=128000
    dim3 gf(B, nseg);
    filter_kernel<<<gf, TPBF, 2 * CHUNK>>>(logits, V);
    select_kernel<<<B, TPBS>>>(sp, V, logits);
    sample_kernel<<<1, 1024>>>(sp, B, (float*)d_out);
}

// round 16
// speedup vs baseline: 1.0959x; 1.0959x over previous
#include <cuda_runtime.h>
#include <cstdint>

#define KSEL   100
#define ESTR   128
#define BMAX   256
#define CAP    2048
#define TPBF   512
#define QB     8
#define SEGQ   (TPBF * QB)     // 4096 quads per filter CTA
#define SEGCAP 128
#define TPBS   256
#define T0     9.0f            // filter threshold; exact fallback covers any input

// Scratch (__device__ globals; zero-init at load; g_cnt reset by select each
// invocation -> graph replays deterministic; ranks are order-independent).
__device__ int                g_cnt[BMAX];
__device__ unsigned long long g_buf[BMAX * CAP];
__device__ float              g_exps[BMAX * ESTR];
__device__ int                g_inds[BMAX * KSEL];

// Order-preserving float->uint key: bigger float => bigger key.
__device__ __forceinline__ unsigned fkey(float f) {
    unsigned u = __float_as_uint(f);
    return u ^ (unsigned)(((int)u >> 31) | 0x80000000);
}
__device__ __forceinline__ float fkey_inv(unsigned kk) {
    unsigned u = (kk & 0x80000000u) ? (kk ^ 0x80000000u) : ~kk;
    return __uint_as_float(u);
}

// ---------------------------------------------------------------------------
// Kernel 1: threshold filter. QB=8 upfront float4 loads, reduced to per-quad
// max immediately (low regs); quad RELOADED from L1 on rare hit.
// oe=4 CTAs/SM, oe*MLP=32 (was 60-80) to cut cross-CTA queue-contention spread.
// ---------------------------------------------------------------------------
__global__ __launch_bounds__(TPBF)
void filter_kernel(const float* __restrict__ logits, int V) {
    const int b   = blockIdx.x;
    const int s   = blockIdx.y;
    const int tid = threadIdx.x;
    const float*  row = logits + (size_t)b * V;
    const int     V4  = V >> 2;
    const float4* r4  = (const float4*)row;
    const int     s0  = s * SEGQ;

    __shared__ unsigned s_n;
    __shared__ int s_base;
    __shared__ unsigned long long s_loc[SEGCAP];
    if (tid == 0) s_n = 0;
    __syncthreads();

    float m[QB];
    int   id[QB];
    {
        float4 v[QB];
#pragma unroll
        for (int j = 0; j < QB; j++) {
            id[j] = s0 + j * TPBF + tid;
            if (id[j] < V4) v[j] = r4[id[j]];
            else            v[j] = make_float4(-3e38f, -3e38f, -3e38f, -3e38f);
        }
#pragma unroll
        for (int j = 0; j < QB; j++)
            m[j] = fmaxf(fmaxf(v[j].x, v[j].y), fmaxf(v[j].z, v[j].w));
    }
#pragma unroll
    for (int j = 0; j < QB; j++) {
        if (m[j] > T0) {                        // rare (~0.5% of quads)
            float4 w = r4[id[j]];               // L1 hit
            const int base = id[j] * 4;
            float vv[4] = {w.x, w.y, w.z, w.w};
#pragma unroll
            for (int q = 0; q < 4; q++) {
                if (vv[q] > T0) {
                    unsigned p = atomicAdd(&s_n, 1u);
                    if (p < SEGCAP)
                        s_loc[p] = ((unsigned long long)fkey(vv[q]) << 32) |
                                   (unsigned)(0xFFFFFFFFu - (unsigned)(base + q));
                }
            }
        }
    }
    if (s == 0) {                               // scalar tail (V % 4)
        for (int i = V4 * 4 + tid; i < V; i += TPBF) {
            float x = row[i];
            if (x > T0) {
                unsigned p = atomicAdd(&s_n, 1u);
                if (p < SEGCAP)
                    s_loc[p] = ((unsigned long long)fkey(x) << 32) |
                               (unsigned)(0xFFFFFFFFu - (unsigned)i);
            }
        }
    }
    __syncthreads();

    if (tid == 0) {
        unsigned nsu = s_n;
        int add = (nsu > SEGCAP) ? 1000000 : (int)nsu;   // poison -> fallback
        s_base = atomicAdd(&g_cnt[b], add);
    }
    __syncthreads();
    int ns = min((int)s_n, SEGCAP);
    unsigned long long* buf = g_buf + (size_t)b * CAP;
    for (int t = tid; t < ns; t += TPBF) {
        int pos = s_base + t;
        if (pos < CAP) buf[pos] = s_loc[t];
    }
}

// ---------------------------------------------------------------------------
// Kernel 2: rank-by-counting selection (round-11 proven form).
// ---------------------------------------------------------------------------
__global__ __launch_bounds__(TPBS)
void select_kernel(const float* __restrict__ sp, int V,
                   const float* __restrict__ logits) {
    const int b    = blockIdx.x;
    const int tid  = threadIdx.x;
    const int lane = tid & 31;
    const int wid  = tid >> 5;

    __shared__ unsigned long long s_cand[512];
    __shared__ unsigned long long s_top;
    __shared__ unsigned s_nc;
    __shared__ int s_part[TPBS / 32];

    const int n = g_cnt[b];
    __syncthreads();                    // all threads read n before reset
    if (tid == 0) g_cnt[b] = 0;         // reset for next replay

    const float* row = logits + (size_t)b * V;
    int nc;

    if (n >= KSEL && n <= 512) {
        const unsigned long long* buf = g_buf + (size_t)b * CAP;
        s_cand[tid]       = (tid < n)       ? buf[tid]       : 0ull;
        s_cand[tid + 256] = (tid + 256 < n) ? buf[tid + 256] : 0ull;
        nc = n;
        __syncthreads();
    } else {
        // exact fallback: bitwise binary search for the 100th key over the row
        unsigned X = 0;
        for (int bit = 31; bit >= 0; --bit) {
            unsigned trial = X | (1u << bit);
            int local = 0;
            for (int i = tid; i < V; i += TPBS)
                local += (fkey(row[i]) >= trial);
#pragma unroll
            for (int off = 16; off; off >>= 1)
                local += __shfl_down_sync(0xffffffffu, local, off);
            if (lane == 0) s_part[wid] = local;
            __syncthreads();
            int cnt = 0;
#pragma unroll
            for (int w = 0; w < TPBS / 32; w++) cnt += s_part[w];
            __syncthreads();
            if (cnt >= KSEL) X = trial;
        }
        if (tid == 0) s_nc = 0;
        s_cand[tid] = 0ull;
        s_cand[tid + 256] = 0ull;
        __syncthreads();
        for (int i = tid; i < V; i += TPBS) {
            unsigned kk = fkey(row[i]);
            if (kk >= X) {
                unsigned p = atomicAdd(&s_nc, 1u);
                if (p < 512)
                    s_cand[p] = ((unsigned long long)kk << 32) |
                                (unsigned)(0xFFFFFFFFu - (unsigned)i);
            }
        }
        __syncthreads();
        nc = min((int)s_nc, 512);
    }

    // ranks via broadcast loop (all lanes read same address -> conflict-free)
    unsigned long long my0 = s_cand[tid];
    unsigned long long my1 = s_cand[tid + 256];
    int r0 = 0, r1 = 0;
    for (int j = 0; j < nc; j++) {
        unsigned long long cj = s_cand[j];
        r0 += (cj > my0);
        r1 += (cj > my1);
    }
    if (tid < nc       && r0 == 0) s_top = my0;
    if (tid + 256 < nc && r1 == 0) s_top = my1;
    if (tid < ESTR) g_exps[b * ESTR + tid] = 0.f;     // zero-pad exps
    __syncthreads();

    const float v0 = fkey_inv((unsigned)(s_top >> 32));
    const int   k  = min(max((int)sp[b * 3 + 0], 1), KSEL);
    const float T  = sp[b * 3 + 2];
    const float v0T = v0 / T;

    if (tid < nc && r0 < KSEL) {
        float val = fkey_inv((unsigned)(my0 >> 32));
        g_inds[b * KSEL + r0] = (int)(0xFFFFFFFFu - (unsigned)(my0 & 0xFFFFFFFFu));
        g_exps[b * ESTR + r0] = (r0 < k) ? expf(val / T - v0T) : 0.f;
    }
    if (tid + 256 < nc && r1 < KSEL) {
        float val = fkey_inv((unsigned)(my1 >> 32));
        g_inds[b * KSEL + r1] = (int)(0xFFFFFFFFu - (unsigned)(my1 & 0xFFFFFFFFu));
        g_exps[b * ESTR + r1] = (r1 < k) ? expf(val / T - v0T) : 0.f;
    }
}

// ---------------------------------------------------------------------------
// Kernel 3: warp-per-row sampling (round-11 proven form).
// ---------------------------------------------------------------------------
__global__ __launch_bounds__(1024)
void sample_kernel(const float* __restrict__ sp, int B,
                   float* __restrict__ out) {
    const int tid  = threadIdx.x;
    const int w    = tid >> 5;
    const int lane = tid & 31;
    const int NW   = blockDim.x >> 5;
    __shared__ float s_inv[1024];

    for (int r = w; r < B; r += NW) {
        const float* e = g_exps + r * ESTR;
        float s = 0.f;
#pragma unroll
        for (int c = 0; c < 4; c++) s += e[c * 32 + lane];
#pragma unroll
        for (int off = 16; off; off >>= 1)
            s += __shfl_xor_sync(0xffffffffu, s, off);
        if (lane == 0) s_inv[r] = 1.0f / s;   // csum[r][0]
    }
    __syncthreads();

    // jnp.min(csum) over the whole matrix = min_b 1/S_b
    float m = s_inv[0];
    for (int i = 1; i < B; i++) m = fminf(m, s_inv[i]);

    for (int r = w; r < B; r += NW) {
        const float* e = g_exps + r * ESTR;
        int   k    = min(max((int)sp[r * 3 + 0], 1), KSEL);
        float topp = sp[r * 3 + 1];
        float eff  = fmaxf(m, topp);

        float p[4];
        float carry = 0.f;
#pragma unroll
        for (int c = 0; c < 4; c++) {
            float x = e[c * 32 + lane];
#pragma unroll
            for (int off = 1; off < 32; off <<= 1) {
                float y = __shfl_up_sync(0xffffffffu, x, off);
                if (lane >= off) x += y;
            }
            float pv = x + carry;
            p[c] = pv;
            carry = __shfl_sync(0xffffffffu, pv, 31);
        }
        float S = carry;
        float invS = 1.0f / S;

        int ns = 0;
#pragma unroll
        for (int c = 0; c < 4; c++) {
            int gi = c * 32 + lane;
            bool cond = (gi < k) && (p[c] * invS <= eff);
            ns += __popc(__ballot_sync(0xffffffffu, cond));
        }
        if (ns < 1) ns = 1;

        int j = ns - 1, cc = j >> 5, ll = j & 31;
        float t0 = __shfl_sync(0xffffffffu, p[0], ll);
        float t1 = __shfl_sync(0xffffffffu, p[1], ll);
        float t2 = __shfl_sync(0xffffffffu, p[2], ll);
        float t3 = __shfl_sync(0xffffffffu, p[3], ll);
        float S2 = (cc == 0) ? t0 : (cc == 1) ? t1 : (cc == 2) ? t2 : t3;

        float half = 0.5f * S2;
        int cnt = 0;
#pragma unroll
        for (int c = 0; c < 4; c++) {
            int gi = c * 32 + lane;
            bool cond = (gi < ns) && (p[c] < half);
            cnt += __popc(__ballot_sync(0xffffffffu, cond));
        }
        if (cnt > ns - 1) cnt = ns - 1;
        if (cnt < 0) cnt = 0;

        if (lane == 0) out[r] = (float)g_inds[r * KSEL + cnt];
    }
}

// ---------------------------------------------------------------------------
extern "C" void kernel_launch(void* const* d_in, const int* in_sizes, int n_in,
                              void* d_out, int out_size) {
    int li = 0, si = 1;
    if (n_in >= 2 && in_sizes[0] < in_sizes[1]) { li = 1; si = 0; }
    const float* logits = (const float*)d_in[li];
    const float* sp     = (const float*)d_in[si];
    int B = in_sizes[si] / 3;
    int V = in_sizes[li] / B;
    if (B > BMAX) B = BMAX;

    int V4   = V >> 2;
    int nseg = (V4 + SEGQ - 1) / SEGQ;      // 8 for V=128000
    dim3 gf(B, nseg);
    filter_kernel<<<gf, TPBF>>>(logits, V);
    select_kernel<<<B, TPBS>>>(sp, V, logits);
    sample_kernel<<<1, 1024>>>(sp, B, (float*)d_out);
}

// round 17
// speedup vs baseline: 1.1015x; 1.0052x over previous
#include <cuda_runtime.h>
#include <cstdint>

#define KSEL   100
#define ESTR   128
#define BMAX   256
#define CAP    2048
#define TPBF   512
#define QB     8
#define SEGQ   (TPBF * QB)     // 4096 quads per filter CTA
#define SEGCAP 128
#define TPBS   256
#define T0     9.0f            // filter threshold; exact fallback covers any input

// Scratch (__device__ globals; zero-init at load; g_cnt reset by select each
// invocation -> graph replays deterministic; ranks are order-independent).
__device__ int                g_cnt[BMAX];
__device__ unsigned long long g_buf[BMAX * CAP];
__device__ float              g_exps[BMAX * ESTR];
__device__ int                g_inds[BMAX * KSEL];

// Order-preserving float->uint key: bigger float => bigger key.
__device__ __forceinline__ unsigned fkey(float f) {
    unsigned u = __float_as_uint(f);
    return u ^ (unsigned)(((int)u >> 31) | 0x80000000);
}
__device__ __forceinline__ float fkey_inv(unsigned kk) {
    unsigned u = (kk & 0x80000000u) ? (kk ^ 0x80000000u) : ~kk;
    return __uint_as_float(u);
}

// ---------------------------------------------------------------------------
// Kernel 1: threshold filter. QB=8 upfront float4 loads, reduced to per-quad
// max immediately (low regs); quad RELOADED from L1 on rare hit.
// oe=4 CTAs/SM, oe*MLP=32 (was 60-80) to cut cross-CTA queue-contention spread.
// ---------------------------------------------------------------------------
__global__ __launch_bounds__(TPBF)
void filter_kernel(const float* __restrict__ logits, int V) {
    const int b   = blockIdx.x;
    const int s   = blockIdx.y;
    const int tid = threadIdx.x;
    const float*  row = logits + (size_t)b * V;
    const int     V4  = V >> 2;
    const float4* r4  = (const float4*)row;
    const int     s0  = s * SEGQ;

    __shared__ unsigned s_n;
    __shared__ int s_base;
    __shared__ unsigned long long s_loc[SEGCAP];
    if (tid == 0) s_n = 0;
    __syncthreads();

    float m[QB];
    int   id[QB];
    {
        float4 v[QB];
#pragma unroll
        for (int j = 0; j < QB; j++) {
            id[j] = s0 + j * TPBF + tid;
            if (id[j] < V4) v[j] = r4[id[j]];
            else            v[j] = make_float4(-3e38f, -3e38f, -3e38f, -3e38f);
        }
#pragma unroll
        for (int j = 0; j < QB; j++)
            m[j] = fmaxf(fmaxf(v[j].x, v[j].y), fmaxf(v[j].z, v[j].w));
    }
#pragma unroll
    for (int j = 0; j < QB; j++) {
        if (m[j] > T0) {                        // rare (~0.5% of quads)
            float4 w = r4[id[j]];               // L1 hit
            const int base = id[j] * 4;
            float vv[4] = {w.x, w.y, w.z, w.w};
#pragma unroll
            for (int q = 0; q < 4; q++) {
                if (vv[q] > T0) {
                    unsigned p = atomicAdd(&s_n, 1u);
                    if (p < SEGCAP)
                        s_loc[p] = ((unsigned long long)fkey(vv[q]) << 32) |
                                   (unsigned)(0xFFFFFFFFu - (unsigned)(base + q));
                }
            }
        }
    }
    if (s == 0) {                               // scalar tail (V % 4)
        for (int i = V4 * 4 + tid; i < V; i += TPBF) {
            float x = row[i];
            if (x > T0) {
                unsigned p = atomicAdd(&s_n, 1u);
                if (p < SEGCAP)
                    s_loc[p] = ((unsigned long long)fkey(x) << 32) |
                               (unsigned)(0xFFFFFFFFu - (unsigned)i);
            }
        }
    }
    __syncthreads();

    if (tid == 0) {
        unsigned nsu = s_n;
        int add = (nsu > SEGCAP) ? 1000000 : (int)nsu;   // poison -> fallback
        s_base = atomicAdd(&g_cnt[b], add);
    }
    __syncthreads();
    int ns = min((int)s_n, SEGCAP);
    unsigned long long* buf = g_buf + (size_t)b * CAP;
    for (int t = tid; t < ns; t += TPBF) {
        int pos = s_base + t;
        if (pos < CAP) buf[pos] = s_loc[t];
    }
}

// ---------------------------------------------------------------------------
// Kernel 2: rank-by-counting selection (round-11 proven form).
// ---------------------------------------------------------------------------
__global__ __launch_bounds__(TPBS)
void select_kernel(const float* __restrict__ sp, int V,
                   const float* __restrict__ logits) {
    const int b    = blockIdx.x;
    const int tid  = threadIdx.x;
    const int lane = tid & 31;
    const int wid  = tid >> 5;

    __shared__ unsigned long long s_cand[512];
    __shared__ unsigned long long s_top;
    __shared__ unsigned s_nc;
    __shared__ int s_part[TPBS / 32];

    const int n = g_cnt[b];
    __syncthreads();                    // all threads read n before reset
    if (tid == 0) g_cnt[b] = 0;         // reset for next replay

    const float* row = logits + (size_t)b * V;
    int nc;

    if (n >= KSEL && n <= 512) {
        const unsigned long long* buf = g_buf + (size_t)b * CAP;
        s_cand[tid]       = (tid < n)       ? buf[tid]       : 0ull;
        s_cand[tid + 256] = (tid + 256 < n) ? buf[tid + 256] : 0ull;
        nc = n;
        __syncthreads();
    } else {
        // exact fallback: bitwise binary search for the 100th key over the row
        unsigned X = 0;
        for (int bit = 31; bit >= 0; --bit) {
            unsigned trial = X | (1u << bit);
            int local = 0;
            for (int i = tid; i < V; i += TPBS)
                local += (fkey(row[i]) >= trial);
#pragma unroll
            for (int off = 16; off; off >>= 1)
                local += __shfl_down_sync(0xffffffffu, local, off);
            if (lane == 0) s_part[wid] = local;
            __syncthreads();
            int cnt = 0;
#pragma unroll
            for (int w = 0; w < TPBS / 32; w++) cnt += s_part[w];
            __syncthreads();
            if (cnt >= KSEL) X = trial;
        }
        if (tid == 0) s_nc = 0;
        s_cand[tid] = 0ull;
        s_cand[tid + 256] = 0ull;
        __syncthreads();
        for (int i = tid; i < V; i += TPBS) {
            unsigned kk = fkey(row[i]);
            if (kk >= X) {
                unsigned p = atomicAdd(&s_nc, 1u);
                if (p < 512)
                    s_cand[p] = ((unsigned long long)kk << 32) |
                                (unsigned)(0xFFFFFFFFu - (unsigned)i);
            }
        }
        __syncthreads();
        nc = min((int)s_nc, 512);
    }

    // ranks via broadcast loop (all lanes read same address -> conflict-free)
    unsigned long long my0 = s_cand[tid];
    unsigned long long my1 = s_cand[tid + 256];
    int r0 = 0, r1 = 0;
    for (int j = 0; j < nc; j++) {
        unsigned long long cj = s_cand[j];
        r0 += (cj > my0);
        r1 += (cj > my1);
    }
    if (tid < nc       && r0 == 0) s_top = my0;
    if (tid + 256 < nc && r1 == 0) s_top = my1;
    if (tid < ESTR) g_exps[b * ESTR + tid] = 0.f;     // zero-pad exps
    __syncthreads();

    const float v0 = fkey_inv((unsigned)(s_top >> 32));
    const int   k  = min(max((int)sp[b * 3 + 0], 1), KSEL);
    const float T  = sp[b * 3 + 2];
    const float v0T = v0 / T;

    if (tid < nc && r0 < KSEL) {
        float val = fkey_inv((unsigned)(my0 >> 32));
        g_inds[b * KSEL + r0] = (int)(0xFFFFFFFFu - (unsigned)(my0 & 0xFFFFFFFFu));
        g_exps[b * ESTR + r0] = (r0 < k) ? expf(val / T - v0T) : 0.f;
    }
    if (tid + 256 < nc && r1 < KSEL) {
        float val = fkey_inv((unsigned)(my1 >> 32));
        g_inds[b * KSEL + r1] = (int)(0xFFFFFFFFu - (unsigned)(my1 & 0xFFFFFFFFu));
        g_exps[b * ESTR + r1] = (r1 < k) ? expf(val / T - v0T) : 0.f;
    }
}

// ---------------------------------------------------------------------------
// Kernel 3: warp-per-row sampling (round-11 proven form).
// ---------------------------------------------------------------------------
__global__ __launch_bounds__(1024)
void sample_kernel(const float* __restrict__ sp, int B,
                   float* __restrict__ out) {
    const int tid  = threadIdx.x;
    const int w    = tid >> 5;
    const int lane = tid & 31;
    const int NW   = blockDim.x >> 5;
    __shared__ float s_inv[1024];

    for (int r = w; r < B; r += NW) {
        const float* e = g_exps + r * ESTR;
        float s = 0.f;
#pragma unroll
        for (int c = 0; c < 4; c++) s += e[c * 32 + lane];
#pragma unroll
        for (int off = 16; off; off >>= 1)
            s += __shfl_xor_sync(0xffffffffu, s, off);
        if (lane == 0) s_inv[r] = 1.0f / s;   // csum[r][0]
    }
    __syncthreads();

    // jnp.min(csum) over the whole matrix = min_b 1/S_b
    float m = s_inv[0];
    for (int i = 1; i < B; i++) m = fminf(m, s_inv[i]);

    for (int r = w; r < B; r += NW) {
        const float* e = g_exps + r * ESTR;
        int   k    = min(max((int)sp[r * 3 + 0], 1), KSEL);
        float topp = sp[r * 3 + 1];
        float eff  = fmaxf(m, topp);

        float p[4];
        float carry = 0.f;
#pragma unroll
        for (int c = 0; c < 4; c++) {
            float x = e[c * 32 + lane];
#pragma unroll
            for (int off = 1; off < 32; off <<= 1) {
                float y = __shfl_up_sync(0xffffffffu, x, off);
                if (lane >= off) x += y;
            }
            float pv = x + carry;
            p[c] = pv;
            carry = __shfl_sync(0xffffffffu, pv, 31);
        }
        float S = carry;
        float invS = 1.0f / S;

        int ns = 0;
#pragma unroll
        for (int c = 0; c < 4; c++) {
            int gi = c * 32 + lane;
            bool cond = (gi < k) && (p[c] * invS <= eff);
            ns += __popc(__ballot_sync(0xffffffffu, cond));
        }
        if (ns < 1) ns = 1;

        int j = ns - 1, cc = j >> 5, ll = j & 31;
        float t0 = __shfl_sync(0xffffffffu, p[0], ll);
        float t1 = __shfl_sync(0xffffffffu, p[1], ll);
        float t2 = __shfl_sync(0xffffffffu, p[2], ll);
        float t3 = __shfl_sync(0xffffffffu, p[3], ll);
        float S2 = (cc == 0) ? t0 : (cc == 1) ? t1 : (cc == 2) ? t2 : t3;

        float half = 0.5f * S2;
        int cnt = 0;
#pragma unroll
        for (int c = 0; c < 4; c++) {
            int gi = c * 32 + lane;
            bool cond = (gi < ns) && (p[c] < half);
            cnt += __popc(__ballot_sync(0xffffffffu, cond));
        }
        if (cnt > ns - 1) cnt = ns - 1;
        if (cnt < 0) cnt = 0;

        if (lane == 0) out[r] = (float)g_inds[r * KSEL + cnt];
    }
}

// ---------------------------------------------------------------------------
extern "C" void kernel_launch(void* const* d_in, const int* in_sizes, int n_in,
                              void* d_out, int out_size) {
    int li = 0, si = 1;
    if (n_in >= 2 && in_sizes[0] < in_sizes[1]) { li = 1; si = 0; }
    const float* logits = (const float*)d_in[li];
    const float* sp     = (const float*)d_in[si];
    int B = in_sizes[si] / 3;
    int V = in_sizes[li] / B;
    if (B > BMAX) B = BMAX;

    int V4   = V >> 2;
    int nseg = (V4 + SEGQ - 1) / SEGQ;      // 8 for V=128000
    dim3 gf(B, nseg);
    filter_kernel<<<gf, TPBF>>>(logits, V);
    select_kernel<<<B, TPBS>>>(sp, V, logits);
    sample_kernel<<<1, 1024>>>(sp, B, (float*)d_out);
}